// round 1
// baseline (speedup 1.0000x reference)
#include <cuda_runtime.h>
#include <cstddef>

// Problem constants
#define BATCH 64
#define PIX   196
#define ENCD  2048
#define ATTD  512
#define EMBD  512
#define DECD  512
#define VOCAB 20000
#define MAXLN 22
#define TSTEP 21
#define XDIM  3072   // EMBD + ENCD + DECD  (concat [e_t, ctx, h] for gates GEMM)

// ---------------------------------------------------------------------------
// Device scratch (no allocations allowed -> __device__ globals)
// ---------------------------------------------------------------------------
__device__ float g_att1[BATCH * PIX * ATTD];      // 25.7 MB: encoder_out @ enc_att_w + b
__device__ float g_mean[BATCH * ENCD];
__device__ float g_h[BATCH * DECD];
__device__ float g_c[BATCH * DECD];
__device__ float g_hnew[BATCH * DECD];
__device__ float g_alpha[BATCH * PIX];
__device__ float g_ctx[BATCH * ENCD];             // gated context
__device__ float g_x[BATCH * XDIM];               // [e_t | gated ctx | h]
__device__ float g_part[24 * BATCH * 2048];       // split-K partials (max 24 slices x 64 x 2048)

// ---------------------------------------------------------------------------
// mean over pixels: g_mean[b,e] = mean_p enc[b,p,e]
// ---------------------------------------------------------------------------
__global__ void mean_kernel(const float* __restrict__ enc) {
    int b = blockIdx.x;
    int e = blockIdx.y * 256 + threadIdx.x;
    const float* base = enc + (size_t)b * PIX * ENCD + e;
    float s = 0.f;
    #pragma unroll 4
    for (int p = 0; p < PIX; p++) s += base[(size_t)p * ENCD];
    g_mean[b * ENCD + e] = s * (1.0f / PIX);
}

// ---------------------------------------------------------------------------
// Generic batch-64 GEMM with split-K:  part[s][64][N] = X[64, k-slice] @ W[k-slice, N]
// X selected by xsel (device globals). W(k) = k < rows1 ? W1[k] : W2[k-rows1].
// Block: 256 threads, tile 64(M) x 128(N), K chunked by 32 via smem.
// grid = (N/128, K/KS), KS multiple of 32.
// ---------------------------------------------------------------------------
#define XSEL_H    0
#define XSEL_MEAN 1
#define XSEL_X    2

__global__ void gemm64_kernel(int xsel,
                              const float* __restrict__ W1, int rows1,
                              const float* __restrict__ W2,
                              int N, int KS) {
    __shared__ float xs[32][65];
    __shared__ float ws[32][132];
    const float* x;
    int ldx;
    if (xsel == XSEL_H)        { x = g_h;    ldx = DECD; }
    else if (xsel == XSEL_MEAN){ x = g_mean; ldx = ENCD; }
    else                       { x = g_x;    ldx = XDIM; }

    int n0 = blockIdx.x * 128;
    int s  = blockIdx.y;
    int k0 = s * KS;
    int tid = threadIdx.x;
    int tx = tid & 31, ty = tid >> 5;     // tx: n-lane, ty: m-group (8 rows each)

    float acc[8][4];
    #pragma unroll
    for (int i = 0; i < 8; i++)
        #pragma unroll
        for (int j = 0; j < 4; j++) acc[i][j] = 0.f;

    for (int kc = 0; kc < KS; kc += 32) {
        int kbase = k0 + kc;
        // load X chunk: 64 rows x 32 k (transposed into xs[k][m])
        {
            int m = tid >> 2, ks2 = (tid & 3) * 8;
            const float* xp = x + (size_t)m * ldx + kbase + ks2;
            #pragma unroll
            for (int j = 0; j < 8; j++) xs[ks2 + j][m] = xp[j];
        }
        // load W chunk: 32 k x 128 n
        {
            int kk = tid >> 3, nseg = (tid & 7) * 16;
            int kg = kbase + kk;
            const float* wrow = (kg < rows1) ? (W1 + (size_t)kg * N)
                                             : (W2 + (size_t)(kg - rows1) * N);
            #pragma unroll
            for (int j = 0; j < 16; j++) ws[kk][nseg + j] = wrow[n0 + nseg + j];
        }
        __syncthreads();
        #pragma unroll
        for (int kk = 0; kk < 32; kk++) {
            float a[8];
            #pragma unroll
            for (int j = 0; j < 8; j++) a[j] = xs[kk][ty * 8 + j];
            float w0 = ws[kk][tx], w1 = ws[kk][tx + 32];
            float w2 = ws[kk][tx + 64], w3 = ws[kk][tx + 96];
            #pragma unroll
            for (int j = 0; j < 8; j++) {
                acc[j][0] += a[j] * w0;
                acc[j][1] += a[j] * w1;
                acc[j][2] += a[j] * w2;
                acc[j][3] += a[j] * w3;
            }
        }
        __syncthreads();
    }
    #pragma unroll
    for (int j = 0; j < 8; j++) {
        int m = ty * 8 + j;
        float* pp = g_part + ((size_t)(s * BATCH + m)) * N + n0 + tx;
        pp[0]  = acc[j][0];
        pp[32] = acc[j][1];
        pp[64] = acc[j][2];
        pp[96] = acc[j][3];
    }
}

// ---------------------------------------------------------------------------
// finish h0/c0: dst[b,n] = bias[n] + sum_s part[s][b][n]
// ---------------------------------------------------------------------------
__global__ void finish64_kernel(int dsel, const float* __restrict__ bias, int N, int nsplit) {
    float* dst = dsel ? g_c : g_h;
    int b = blockIdx.x;
    for (int n = threadIdx.x; n < N; n += blockDim.x) {
        float v = bias[n];
        for (int s = 0; s < nsplit; s++) v += g_part[(size_t)(s * BATCH + b) * N + n];
        dst[b * N + n] = v;
    }
}

// ---------------------------------------------------------------------------
// att1 GEMM (one-time): g_att1 = encoder_out(12544x2048) @ enc_att_w(2048x512) + b
// 128x128 tile, 8x8 micro, 256 threads. grid (98, 4).
// ---------------------------------------------------------------------------
__global__ void att1_kernel(const float* __restrict__ A, const float* __restrict__ Bm,
                            const float* __restrict__ bias) {
    __shared__ float As[16][132];
    __shared__ float Bs[16][132];
    int m0 = blockIdx.x * 128, n0 = blockIdx.y * 128;
    int tid = threadIdx.x;
    int tx = tid & 15, ty = tid >> 4;

    float acc[8][8];
    #pragma unroll
    for (int i = 0; i < 8; i++)
        #pragma unroll
        for (int j = 0; j < 8; j++) acc[i][j] = 0.f;

    for (int k0 = 0; k0 < ENCD; k0 += 16) {
        {
            int row = tid >> 1, ks2 = (tid & 1) * 8;
            const float* ap = A + (size_t)(m0 + row) * ENCD + k0 + ks2;
            #pragma unroll
            for (int j = 0; j < 8; j++) As[ks2 + j][row] = ap[j];
        }
        {
            int kk = tid >> 4, nn = (tid & 15) * 8;
            const float* bp = Bm + (size_t)(k0 + kk) * ATTD + n0 + nn;
            #pragma unroll
            for (int j = 0; j < 8; j++) Bs[kk][nn + j] = bp[j];
        }
        __syncthreads();
        #pragma unroll
        for (int kk = 0; kk < 16; kk++) {
            float a[8], bb[8];
            #pragma unroll
            for (int i = 0; i < 4; i++) {
                a[i]      = As[kk][ty * 4 + i];
                a[4 + i]  = As[kk][64 + ty * 4 + i];
                bb[i]     = Bs[kk][tx * 4 + i];
                bb[4 + i] = Bs[kk][64 + tx * 4 + i];
            }
            #pragma unroll
            for (int i = 0; i < 8; i++)
                #pragma unroll
                for (int j = 0; j < 8; j++) acc[i][j] += a[i] * bb[j];
        }
        __syncthreads();
    }
    #pragma unroll
    for (int i = 0; i < 8; i++) {
        int m = m0 + ((i < 4) ? (ty * 4 + i) : (64 + ty * 4 + i - 4));
        float* crow = g_att1 + (size_t)m * ATTD + n0;
        #pragma unroll
        for (int j = 0; j < 8; j++) {
            int nn = (j < 4) ? (tx * 4 + j) : (64 + tx * 4 + j - 4);
            crow[nn] = acc[i][j] + bias[n0 + nn];
        }
    }
}

// ---------------------------------------------------------------------------
// scores + softmax per batch element. Consumes att2 split-K partials.
// scores[p] = sum_a relu(att1[b,p,a] + att2[b,a]) * fw[a] + fb;  alpha = softmax
// ---------------------------------------------------------------------------
__global__ void attn_scores_kernel(const float* __restrict__ dec_att_b,
                                   const float* __restrict__ full_att_w,
                                   const float* __restrict__ full_att_b,
                                   const int* __restrict__ lengths,
                                   float* __restrict__ out_alpha, int t, int nsplit) {
    __shared__ float att2s[ATTD];
    __shared__ float fws[ATTD];
    __shared__ float sc[PIX];
    __shared__ float red[8];
    int b = blockIdx.x, tid = threadIdx.x;

    for (int a = tid; a < ATTD; a += 256) {
        float v = dec_att_b[a];
        for (int s = 0; s < nsplit; s++) v += g_part[(size_t)(s * BATCH + b) * ATTD + a];
        att2s[a] = v;
        fws[a] = full_att_w[a];
    }
    __syncthreads();

    int warp = tid >> 5, lane = tid & 31;
    for (int p = warp; p < PIX; p += 8) {
        const float* arow = g_att1 + ((size_t)(b * PIX + p)) * ATTD;
        float s = 0.f;
        for (int a = lane; a < ATTD; a += 32) {
            float v = arow[a] + att2s[a];
            s += fmaxf(v, 0.f) * fws[a];
        }
        #pragma unroll
        for (int o = 16; o; o >>= 1) s += __shfl_xor_sync(~0u, s, o);
        if (!lane) sc[p] = s + full_att_b[0];
    }
    __syncthreads();

    float v = (tid < PIX) ? sc[tid] : -1e30f;
    float m = v;
    #pragma unroll
    for (int o = 16; o; o >>= 1) m = fmaxf(m, __shfl_xor_sync(~0u, m, o));
    if (!lane) red[warp] = m;
    __syncthreads();
    if (tid == 0) {
        float mm = red[0];
        for (int i = 1; i < 8; i++) mm = fmaxf(mm, red[i]);
        red[0] = mm;
    }
    __syncthreads();
    float mx = red[0];
    float e = (tid < PIX) ? __expf(v - mx) : 0.f;
    float s2 = e;
    #pragma unroll
    for (int o = 16; o; o >>= 1) s2 += __shfl_xor_sync(~0u, s2, o);
    __syncthreads();                 // done reading red[0]
    if (!lane) red[warp] = s2;
    __syncthreads();
    if (tid == 0) {
        float ss = 0.f;
        for (int i = 0; i < 8; i++) ss += red[i];
        red[0] = ss;
    }
    __syncthreads();
    float inv = 1.f / red[0];
    if (tid < PIX) {
        float al = e * inv;
        g_alpha[b * PIX + tid] = al;
        bool active = t < (lengths[b] - 1);
        out_alpha[((size_t)b * TSTEP + t) * PIX + tid] = active ? al : 0.f;
    }
}

// ---------------------------------------------------------------------------
// context + gate: g_ctx[b,e] = sigmoid(h@f_beta_w + b)[e] * sum_p alpha[p]*enc[b,p,e]
// (gate pre-activation comes in as split-K partials). grid(64, 4), 256 thr.
// ---------------------------------------------------------------------------
__global__ void ctx_gate_kernel(const float* __restrict__ enc,
                                const float* __restrict__ f_beta_b, int nsplit) {
    __shared__ float als[PIX];
    int b = blockIdx.x, q = blockIdx.y, tid = threadIdx.x;
    if (tid < PIX) als[tid] = g_alpha[b * PIX + tid];
    __syncthreads();
    int e0 = q * 512;
    #pragma unroll
    for (int i = 0; i < 2; i++) {
        int e = e0 + tid + i * 256;
        const float* base = enc + (size_t)b * PIX * ENCD + e;
        float csum = 0.f;
        #pragma unroll 4
        for (int p = 0; p < PIX; p++) csum += als[p] * base[(size_t)p * ENCD];
        float gp = f_beta_b[e];
        for (int s = 0; s < nsplit; s++) gp += g_part[(size_t)(s * BATCH + b) * ENCD + e];
        float gate = 1.f / (1.f + __expf(-gp));
        g_ctx[b * ENCD + e] = gate * csum;
    }
}

// ---------------------------------------------------------------------------
// build x = [emb[cap], gated ctx, h]
// ---------------------------------------------------------------------------
__global__ void build_x_kernel(const float* __restrict__ emb,
                               const int* __restrict__ captions, int t) {
    int b = blockIdx.x, tid = threadIdx.x;
    int cap = captions[b * MAXLN + t];
    for (int i = tid; i < XDIM; i += 256) {
        float v;
        if (i < EMBD)             v = emb[(size_t)cap * EMBD + i];
        else if (i < EMBD + ENCD) v = g_ctx[b * ENCD + (i - EMBD)];
        else                      v = g_h[b * DECD + (i - EMBD - ENCD)];
        g_x[b * XDIM + i] = v;
    }
}

// ---------------------------------------------------------------------------
// LSTM pointwise: sum gate partials + biases, apply i,f,g,o; masked h/c update.
// ---------------------------------------------------------------------------
__global__ void lstm_kernel(const float* __restrict__ b_ih, const float* __restrict__ b_hh,
                            const int* __restrict__ lengths, int t, int nsplit) {
    int b = blockIdx.x, d = threadIdx.x;   // 512 threads
    float g4[4];
    #pragma unroll
    for (int gi = 0; gi < 4; gi++) {
        int n = gi * 512 + d;
        float v = b_ih[n] + b_hh[n];
        for (int s = 0; s < nsplit; s++) v += g_part[(size_t)(s * BATCH + b) * 2048 + n];
        g4[gi] = v;
    }
    float ig = 1.f / (1.f + __expf(-g4[0]));
    float fg = 1.f / (1.f + __expf(-g4[1]));
    float gg = tanhf(g4[2]);
    float og = 1.f / (1.f + __expf(-g4[3]));
    float cold = g_c[b * DECD + d];
    float cn = fg * cold + ig * gg;
    float hn = og * tanhf(cn);
    g_hnew[b * DECD + d] = hn;
    if (t < (lengths[b] - 1)) {
        g_h[b * DECD + d] = hn;
        g_c[b * DECD + d] = cn;
    }
}

// ---------------------------------------------------------------------------
// fc: preds[b,t,:] = active ? h_new @ fc_w + fc_b : 0.  64x128 tile, K=512.
// grid(157), 256 threads, each thread 4(M)x8(N).
// ---------------------------------------------------------------------------
__global__ void fc_kernel(const float* __restrict__ fc_w, const float* __restrict__ fc_b,
                          const int* __restrict__ lengths, float* __restrict__ out, int t) {
    __shared__ float hs[16][64];
    __shared__ float ws[16][132];
    int n0 = blockIdx.x * 128;
    int tid = threadIdx.x;
    int tx = tid & 15, ty = tid >> 4;

    float acc[4][8];
    #pragma unroll
    for (int i = 0; i < 4; i++)
        #pragma unroll
        for (int j = 0; j < 8; j++) acc[i][j] = 0.f;

    for (int k0 = 0; k0 < DECD; k0 += 16) {
        {
            int idx = tid * 4;
            int m = idx >> 4, kk = idx & 15;
            const float* hp = g_hnew + (size_t)m * DECD + k0 + kk;
            #pragma unroll
            for (int j = 0; j < 4; j++) hs[kk + j][m] = hp[j];
        }
        {
            int idx = tid * 8;
            int kk = idx >> 7, nn = idx & 127;
            const float* wp = fc_w + (size_t)(k0 + kk) * VOCAB + n0 + nn;
            #pragma unroll
            for (int j = 0; j < 8; j++)
                ws[kk][nn + j] = (n0 + nn + j < VOCAB) ? wp[j] : 0.f;
        }
        __syncthreads();
        #pragma unroll
        for (int kk = 0; kk < 16; kk++) {
            float a0 = hs[kk][ty * 4 + 0], a1 = hs[kk][ty * 4 + 1];
            float a2 = hs[kk][ty * 4 + 2], a3 = hs[kk][ty * 4 + 3];
            #pragma unroll
            for (int j = 0; j < 8; j++) {
                float w = ws[kk][tx + 16 * j];
                acc[0][j] += a0 * w;
                acc[1][j] += a1 * w;
                acc[2][j] += a2 * w;
                acc[3][j] += a3 * w;
            }
        }
        __syncthreads();
    }
    #pragma unroll
    for (int i = 0; i < 4; i++) {
        int m = ty * 4 + i;                          // batch index
        bool active = t < (lengths[m] - 1);
        float* orow = out + ((size_t)m * TSTEP + t) * VOCAB;
        #pragma unroll
        for (int j = 0; j < 8; j++) {
            int n = n0 + tx + 16 * j;
            if (n < VOCAB) orow[n] = active ? (acc[i][j] + fc_b[n]) : 0.f;
        }
    }
}

// ---------------------------------------------------------------------------
// Host launcher. Input order per setup_inputs(); output = preds then alphas.
// ---------------------------------------------------------------------------
extern "C" void kernel_launch(void* const* d_in, const int* in_sizes, int n_in,
                              void* d_out, int out_size) {
    const float* enc        = (const float*)d_in[0];
    const int*   captions   = (const int*)  d_in[1];
    const int*   lengths    = (const int*)  d_in[2];
    const float* emb        = (const float*)d_in[3];
    const float* enc_att_w  = (const float*)d_in[4];
    const float* enc_att_b  = (const float*)d_in[5];
    const float* dec_att_w  = (const float*)d_in[6];
    const float* dec_att_b  = (const float*)d_in[7];
    const float* full_att_w = (const float*)d_in[8];
    const float* full_att_b = (const float*)d_in[9];
    const float* w_ih       = (const float*)d_in[10];
    const float* b_ih       = (const float*)d_in[11];
    const float* w_hh       = (const float*)d_in[12];
    const float* b_hh       = (const float*)d_in[13];
    const float* init_h_w   = (const float*)d_in[14];
    const float* init_h_b   = (const float*)d_in[15];
    const float* init_c_w   = (const float*)d_in[16];
    const float* init_c_b   = (const float*)d_in[17];
    const float* f_beta_w   = (const float*)d_in[18];
    const float* f_beta_b   = (const float*)d_in[19];
    const float* fc_w       = (const float*)d_in[20];
    const float* fc_b       = (const float*)d_in[21];

    float* out       = (float*)d_out;
    float* out_alpha = out + (size_t)BATCH * TSTEP * VOCAB;

    // ---- setup ----
    mean_kernel<<<dim3(BATCH, ENCD / 256), 256>>>(enc);

    // h0 = mean @ init_h_w + b ; c0 likewise (split-K GEMM + finish)
    gemm64_kernel<<<dim3(4, 16), 256>>>(XSEL_MEAN, init_h_w, ENCD, nullptr, DECD, 128);
    finish64_kernel<<<BATCH, 512>>>(0, init_h_b, DECD, 16);
    gemm64_kernel<<<dim3(4, 16), 256>>>(XSEL_MEAN, init_c_w, ENCD, nullptr, DECD, 128);
    finish64_kernel<<<BATCH, 512>>>(1, init_c_b, DECD, 16);

    // att1 (one-time big GEMM)
    att1_kernel<<<dim3((BATCH * PIX) / 128, ATTD / 128), 256>>>(enc, enc_att_w, enc_att_b);

    // ---- decode steps ----
    for (int t = 0; t < TSTEP; t++) {
        // att2 = h @ dec_att_w  (64x512, K=512; 8 K-slices of 64)
        gemm64_kernel<<<dim3(ATTD / 128, 8), 256>>>(XSEL_H, dec_att_w, DECD, nullptr, ATTD, 64);
        attn_scores_kernel<<<BATCH, 256>>>(dec_att_b, full_att_w, full_att_b,
                                           lengths, out_alpha, t, 8);
        // gate_pre = h @ f_beta_w  (64x2048, K=512)
        gemm64_kernel<<<dim3(ENCD / 128, 8), 256>>>(XSEL_H, f_beta_w, DECD, nullptr, ENCD, 64);
        ctx_gate_kernel<<<dim3(BATCH, 4), 256>>>(enc, f_beta_b, 8);
        build_x_kernel<<<BATCH, 256>>>(emb, captions, t);
        // gates = [e_t|ctx] @ w_ih + h @ w_hh  (64x2048, K=3072; 24 slices of 128)
        gemm64_kernel<<<dim3(2048 / 128, 24), 256>>>(XSEL_X, w_ih, EMBD + ENCD, w_hh, 2048, 128);
        lstm_kernel<<<BATCH, 512>>>(b_ih, b_hh, lengths, t, 24);
        // preds = h_new @ fc_w + fc_b (masked)
        fc_kernel<<<(VOCAB + 127) / 128, 256>>>(fc_w, fc_b, lengths, out, t);
    }
}

// round 2
// speedup vs baseline: 1.6006x; 1.6006x over previous
#include <cuda_runtime.h>
#include <cstdint>
#include <cstddef>

#define BATCH 64
#define PIX   196
#define ENCD  2048
#define ATTD  512
#define EMBD  512
#define DECD  512
#define VOCAB 20000
#define MAXLN 22
#define TSTEP 21
#define XDIM  3072

__device__ float g_att1[BATCH * PIX * ATTD];
__device__ float g_mean[BATCH * ENCD];
__device__ float g_h[BATCH * DECD];
__device__ float g_c[BATCH * DECD];
__device__ float g_hnew[BATCH * DECD];
__device__ float g_alpha[BATCH * PIX];
__device__ float g_x[BATCH * XDIM];
__device__ float g_part[16 * BATCH * 2560];

__device__ __forceinline__ uint32_t cvt_tf32(float f) {
    uint32_t u;
    asm("cvt.rna.tf32.f32 %0, %1;" : "=r"(u) : "f"(f));
    return u;
}

__device__ __forceinline__ void mma_tf32(float* d, const uint32_t* a, const uint32_t* b) {
    asm volatile(
        "mma.sync.aligned.m16n8k8.row.col.f32.tf32.tf32.f32 "
        "{%0,%1,%2,%3}, {%4,%5,%6,%7}, {%8,%9}, {%0,%1,%2,%3};\n"
        : "+f"(d[0]), "+f"(d[1]), "+f"(d[2]), "+f"(d[3])
        : "r"(a[0]), "r"(a[1]), "r"(a[2]), "r"(a[3]), "r"(b[0]), "r"(b[1]));
}

__global__ void mean_kernel(const float* __restrict__ enc) {
    int b = blockIdx.x;
    int e = blockIdx.y * 256 + threadIdx.x;
    const float* base = enc + (size_t)b * PIX * ENCD + e;
    float s = 0.f;
    #pragma unroll 4
    for (int p = 0; p < PIX; p++) s += base[(size_t)p * ENCD];
    g_mean[b * ENCD + e] = s * (1.0f / PIX);
}

// X source selector (device globals can't be passed from host reliably pre-launch)
#define XSEL_H    0
#define XSEL_MEAN 1
#define XSEL_X    2

// M=64 tf32 GEMM, split-K, N-concat (Wa cols [0,na), Wb rest) and
// K-concat (rows >= rows1 from W2k). Tile 64x128, 256 threads.
__global__ void gemm64_tc(int xsel, int ldx,
                          const float* __restrict__ Wa, int lda, int na,
                          const float* __restrict__ Wb, int ldb,
                          int rows1, const float* __restrict__ W2k,
                          int N, int KS)
{
    __shared__ uint32_t As[64 * 36];
    __shared__ uint32_t Bs[32 * 136];
    const float* X = (xsel == XSEL_H) ? g_h : (xsel == XSEL_MEAN) ? g_mean : g_x;
    int n0 = blockIdx.x * 128;
    int s  = blockIdx.y;
    int tid = threadIdx.x;
    int lane = tid & 31, warp = tid >> 5;
    int wm = warp >> 2, wn = warp & 3;
    int g = lane >> 2, t4 = lane & 3;

    const float* Wsel; int ld, coloff;
    if (n0 < na) { Wsel = Wa; ld = lda; coloff = n0; }
    else         { Wsel = Wb; ld = ldb; coloff = n0 - na; }

    float acc[2][4][4];
    #pragma unroll
    for (int i = 0; i < 2; i++)
        #pragma unroll
        for (int j = 0; j < 4; j++)
            #pragma unroll
            for (int q = 0; q < 4; q++) acc[i][j][q] = 0.f;

    int ar = tid >> 2, ak = (tid & 3) * 8;
    int bk = tid >> 3, bn = (tid & 7) * 16;

    for (int kc = 0; kc < KS; kc += 32) {
        int kbase = s * KS + kc;
        {
            const float* xp = X + (size_t)ar * ldx + kbase + ak;
            float4 v0 = *(const float4*)xp;
            float4 v1 = *(const float4*)(xp + 4);
            uint32_t* dst = As + ar * 36 + ak;
            dst[0] = cvt_tf32(v0.x); dst[1] = cvt_tf32(v0.y);
            dst[2] = cvt_tf32(v0.z); dst[3] = cvt_tf32(v0.w);
            dst[4] = cvt_tf32(v1.x); dst[5] = cvt_tf32(v1.y);
            dst[6] = cvt_tf32(v1.z); dst[7] = cvt_tf32(v1.w);
        }
        {
            int kg = kbase + bk;
            const float* wrow = (kg < rows1)
                ? (Wsel + (size_t)kg * ld + coloff)
                : (W2k + (size_t)(kg - rows1) * ld + coloff);
            uint32_t* dst = Bs + bk * 136 + bn;
            #pragma unroll
            for (int j = 0; j < 4; j++) {
                float4 v = *(const float4*)(wrow + bn + j * 4);
                dst[j*4+0] = cvt_tf32(v.x); dst[j*4+1] = cvt_tf32(v.y);
                dst[j*4+2] = cvt_tf32(v.z); dst[j*4+3] = cvt_tf32(v.w);
            }
        }
        __syncthreads();
        #pragma unroll
        for (int kk = 0; kk < 32; kk += 8) {
            uint32_t afr[2][4], bfr[4][2];
            #pragma unroll
            for (int mt = 0; mt < 2; mt++) {
                int m = wm * 32 + mt * 16;
                const uint32_t* a0 = As + (m + g) * 36 + kk + t4;
                const uint32_t* a1 = As + (m + g + 8) * 36 + kk + t4;
                afr[mt][0] = a0[0]; afr[mt][1] = a1[0];
                afr[mt][2] = a0[4]; afr[mt][3] = a1[4];
            }
            #pragma unroll
            for (int nt = 0; nt < 4; nt++) {
                int n = wn * 32 + nt * 8 + g;
                bfr[nt][0] = Bs[(kk + t4) * 136 + n];
                bfr[nt][1] = Bs[(kk + t4 + 4) * 136 + n];
            }
            #pragma unroll
            for (int mt = 0; mt < 2; mt++)
                #pragma unroll
                for (int nt = 0; nt < 4; nt++)
                    mma_tf32(acc[mt][nt], afr[mt], bfr[nt]);
        }
        __syncthreads();
    }
    #pragma unroll
    for (int mt = 0; mt < 2; mt++) {
        int row = wm * 32 + mt * 16 + g;
        #pragma unroll
        for (int nt = 0; nt < 4; nt++) {
            int col = n0 + wn * 32 + nt * 8 + 2 * t4;
            float* p0 = g_part + (size_t)(s * BATCH + row) * N + col;
            p0[0] = acc[mt][nt][0]; p0[1] = acc[mt][nt][1];
            float* p1 = p0 + (size_t)8 * N;
            p1[0] = acc[mt][nt][2]; p1[1] = acc[mt][nt][3];
        }
    }
}

__global__ void finish64_kernel(int dsel, const float* __restrict__ bias, int N, int nsplit) {
    float* dst = dsel ? g_c : g_h;
    int b = blockIdx.x;
    for (int n = threadIdx.x; n < N; n += blockDim.x) {
        float v = bias[n];
        for (int s = 0; s < nsplit; s++) v += g_part[(size_t)(s * BATCH + b) * N + n];
        dst[b * N + n] = v;
    }
}

__global__ void att1_tc(const float* __restrict__ A, const float* __restrict__ W,
                        const float* __restrict__ bias) {
    __shared__ uint32_t As[128 * 36];
    __shared__ uint32_t Bs[32 * 136];
    int m0 = blockIdx.x * 128, n0 = blockIdx.y * 128;
    int tid = threadIdx.x;
    int lane = tid & 31, warp = tid >> 5;
    int wm = warp >> 2, wn = warp & 3;
    int g = lane >> 2, t4 = lane & 3;

    float acc[4][4][4];
    #pragma unroll
    for (int i = 0; i < 4; i++)
        #pragma unroll
        for (int j = 0; j < 4; j++)
            #pragma unroll
            for (int q = 0; q < 4; q++) acc[i][j][q] = 0.f;

    int ar = tid >> 1, ak = (tid & 1) * 16;
    int bk = tid >> 3, bn = (tid & 7) * 16;

    for (int kbase = 0; kbase < ENCD; kbase += 32) {
        {
            const float* ap = A + (size_t)(m0 + ar) * ENCD + kbase + ak;
            uint32_t* dst = As + ar * 36 + ak;
            #pragma unroll
            for (int j = 0; j < 4; j++) {
                float4 v = *(const float4*)(ap + j * 4);
                dst[j*4+0] = cvt_tf32(v.x); dst[j*4+1] = cvt_tf32(v.y);
                dst[j*4+2] = cvt_tf32(v.z); dst[j*4+3] = cvt_tf32(v.w);
            }
        }
        {
            const float* wrow = W + (size_t)(kbase + bk) * ATTD + n0;
            uint32_t* dst = Bs + bk * 136 + bn;
            #pragma unroll
            for (int j = 0; j < 4; j++) {
                float4 v = *(const float4*)(wrow + bn + j * 4);
                dst[j*4+0] = cvt_tf32(v.x); dst[j*4+1] = cvt_tf32(v.y);
                dst[j*4+2] = cvt_tf32(v.z); dst[j*4+3] = cvt_tf32(v.w);
            }
        }
        __syncthreads();
        #pragma unroll
        for (int kk = 0; kk < 32; kk += 8) {
            uint32_t afr[4][4], bfr[4][2];
            #pragma unroll
            for (int mt = 0; mt < 4; mt++) {
                int m = wm * 64 + mt * 16;
                const uint32_t* a0 = As + (m + g) * 36 + kk + t4;
                const uint32_t* a1 = As + (m + g + 8) * 36 + kk + t4;
                afr[mt][0] = a0[0]; afr[mt][1] = a1[0];
                afr[mt][2] = a0[4]; afr[mt][3] = a1[4];
            }
            #pragma unroll
            for (int nt = 0; nt < 4; nt++) {
                int n = wn * 32 + nt * 8 + g;
                bfr[nt][0] = Bs[(kk + t4) * 136 + n];
                bfr[nt][1] = Bs[(kk + t4 + 4) * 136 + n];
            }
            #pragma unroll
            for (int mt = 0; mt < 4; mt++)
                #pragma unroll
                for (int nt = 0; nt < 4; nt++)
                    mma_tf32(acc[mt][nt], afr[mt], bfr[nt]);
        }
        __syncthreads();
    }
    #pragma unroll
    for (int mt = 0; mt < 4; mt++) {
        int row = m0 + wm * 64 + mt * 16 + g;
        #pragma unroll
        for (int nt = 0; nt < 4; nt++) {
            int col = n0 + wn * 32 + nt * 8 + 2 * t4;
            float b0 = bias[col], b1 = bias[col + 1];
            float* p0 = g_att1 + (size_t)row * ATTD + col;
            p0[0] = acc[mt][nt][0] + b0; p0[1] = acc[mt][nt][1] + b1;
            float* p1 = p0 + (size_t)8 * ATTD;
            p1[0] = acc[mt][nt][2] + b0; p1[1] = acc[mt][nt][3] + b1;
        }
    }
}

__global__ void attn_scores_kernel(const float* __restrict__ dec_att_b,
                                   const float* __restrict__ full_att_w,
                                   const float* __restrict__ full_att_b,
                                   const int* __restrict__ lengths,
                                   float* __restrict__ out_alpha, int t, int nsplit) {
    __shared__ float att2s[ATTD];
    __shared__ float fws[ATTD];
    __shared__ float sc[PIX];
    __shared__ float red[8];
    int b = blockIdx.x, tid = threadIdx.x;

    for (int a = tid; a < ATTD; a += 256) {
        float v = dec_att_b[a];
        for (int s = 0; s < nsplit; s++) v += g_part[(size_t)(s * BATCH + b) * 2560 + a];
        att2s[a] = v;
        fws[a] = full_att_w[a];
    }
    __syncthreads();

    int warp = tid >> 5, lane = tid & 31;
    for (int p = warp; p < PIX; p += 8) {
        const float* arow = g_att1 + ((size_t)(b * PIX + p)) * ATTD;
        float s = 0.f;
        for (int a = lane; a < ATTD; a += 32) {
            float v = arow[a] + att2s[a];
            s += fmaxf(v, 0.f) * fws[a];
        }
        #pragma unroll
        for (int o = 16; o; o >>= 1) s += __shfl_xor_sync(~0u, s, o);
        if (!lane) sc[p] = s + full_att_b[0];
    }
    __syncthreads();

    float v = (tid < PIX) ? sc[tid] : -1e30f;
    float m = v;
    #pragma unroll
    for (int o = 16; o; o >>= 1) m = fmaxf(m, __shfl_xor_sync(~0u, m, o));
    if (!lane) red[warp] = m;
    __syncthreads();
    if (tid == 0) {
        float mm = red[0];
        for (int i = 1; i < 8; i++) mm = fmaxf(mm, red[i]);
        red[0] = mm;
    }
    __syncthreads();
    float mx = red[0];
    float e = (tid < PIX) ? __expf(v - mx) : 0.f;
    float s2 = e;
    #pragma unroll
    for (int o = 16; o; o >>= 1) s2 += __shfl_xor_sync(~0u, s2, o);
    __syncthreads();
    if (!lane) red[warp] = s2;
    __syncthreads();
    if (tid == 0) {
        float ss = 0.f;
        for (int i = 0; i < 8; i++) ss += red[i];
        red[0] = ss;
    }
    __syncthreads();
    float inv = 1.f / red[0];
    if (tid < PIX) {
        float al = e * inv;
        g_alpha[b * PIX + tid] = al;
        bool active = t < (lengths[b] - 1);
        out_alpha[((size_t)b * TSTEP + t) * PIX + tid] = active ? al : 0.f;
    }
}

__global__ void ctx_gate_kernel(const float* __restrict__ enc,
                                const float* __restrict__ f_beta_b, int nsplit) {
    __shared__ float als[PIX];
    int b = blockIdx.x, q = blockIdx.y, tid = threadIdx.x;
    if (tid < PIX) als[tid] = g_alpha[b * PIX + tid];
    __syncthreads();
    int e0 = q * 512;
    #pragma unroll
    for (int i = 0; i < 2; i++) {
        int e = e0 + tid + i * 256;
        const float* base = enc + (size_t)b * PIX * ENCD + e;
        float csum = 0.f;
        #pragma unroll 4
        for (int p = 0; p < PIX; p++) csum += als[p] * base[(size_t)p * ENCD];
        float gp = f_beta_b[e];
        for (int s = 0; s < nsplit; s++)
            gp += g_part[(size_t)(s * BATCH + b) * 2560 + 512 + e];
        float gate = 1.f / (1.f + __expf(-gp));
        g_x[b * XDIM + EMBD + e] = gate * csum;
    }
}

__global__ void build_x_kernel(const float* __restrict__ emb,
                               const int* __restrict__ captions, int t) {
    int b = blockIdx.x, tid = threadIdx.x;
    int cap = captions[b * MAXLN + t];
    for (int i = tid; i < EMBD; i += 256) {
        g_x[b * XDIM + i] = emb[(size_t)cap * EMBD + i];
        g_x[b * XDIM + EMBD + ENCD + i] = g_h[b * DECD + i];
    }
}

__global__ void lstm_kernel(const float* __restrict__ b_ih, const float* __restrict__ b_hh,
                            const int* __restrict__ lengths, int t, int nsplit) {
    int b = blockIdx.x, d = threadIdx.x;
    float g4[4];
    #pragma unroll
    for (int gi = 0; gi < 4; gi++) {
        int n = gi * 512 + d;
        float v = b_ih[n] + b_hh[n];
        for (int s = 0; s < nsplit; s++) v += g_part[(size_t)(s * BATCH + b) * 2048 + n];
        g4[gi] = v;
    }
    float ig = 1.f / (1.f + __expf(-g4[0]));
    float fg = 1.f / (1.f + __expf(-g4[1]));
    float gg = tanhf(g4[2]);
    float og = 1.f / (1.f + __expf(-g4[3]));
    float cold = g_c[b * DECD + d];
    float cn = fg * cold + ig * gg;
    float hn = og * tanhf(cn);
    g_hnew[b * DECD + d] = hn;
    if (t < (lengths[b] - 1)) {
        g_h[b * DECD + d] = hn;
        g_c[b * DECD + d] = cn;
    }
}

__global__ void fc_tc(const float* __restrict__ W, const float* __restrict__ bias,
                      const int* __restrict__ lengths, float* __restrict__ out, int t) {
    __shared__ uint32_t As[64 * 36];
    __shared__ uint32_t Bs[32 * 136];
    int n0 = blockIdx.x * 128;
    int tid = threadIdx.x;
    int lane = tid & 31, warp = tid >> 5;
    int wm = warp >> 2, wn = warp & 3;
    int g = lane >> 2, t4 = lane & 3;
    bool full = (n0 + 128 <= VOCAB);

    float acc[2][4][4];
    #pragma unroll
    for (int i = 0; i < 2; i++)
        #pragma unroll
        for (int j = 0; j < 4; j++)
            #pragma unroll
            for (int q = 0; q < 4; q++) acc[i][j][q] = 0.f;

    int ar = tid >> 2, ak = (tid & 3) * 8;
    int bk = tid >> 3, bn = (tid & 7) * 16;

    for (int kbase = 0; kbase < DECD; kbase += 32) {
        {
            const float* xp = g_hnew + (size_t)ar * DECD + kbase + ak;
            float4 v0 = *(const float4*)xp;
            float4 v1 = *(const float4*)(xp + 4);
            uint32_t* dst = As + ar * 36 + ak;
            dst[0] = cvt_tf32(v0.x); dst[1] = cvt_tf32(v0.y);
            dst[2] = cvt_tf32(v0.z); dst[3] = cvt_tf32(v0.w);
            dst[4] = cvt_tf32(v1.x); dst[5] = cvt_tf32(v1.y);
            dst[6] = cvt_tf32(v1.z); dst[7] = cvt_tf32(v1.w);
        }
        {
            const float* wrow = W + (size_t)(kbase + bk) * VOCAB + n0;
            uint32_t* dst = Bs + bk * 136 + bn;
            if (full) {
                #pragma unroll
                for (int j = 0; j < 4; j++) {
                    float4 v = *(const float4*)(wrow + bn + j * 4);
                    dst[j*4+0] = cvt_tf32(v.x); dst[j*4+1] = cvt_tf32(v.y);
                    dst[j*4+2] = cvt_tf32(v.z); dst[j*4+3] = cvt_tf32(v.w);
                }
            } else {
                #pragma unroll
                for (int j = 0; j < 16; j++) {
                    int n = bn + j;
                    float v = (n0 + n < VOCAB) ? wrow[n] : 0.f;
                    dst[j] = cvt_tf32(v);
                }
            }
        }
        __syncthreads();
        #pragma unroll
        for (int kk = 0; kk < 32; kk += 8) {
            uint32_t afr[2][4], bfr[4][2];
            #pragma unroll
            for (int mt = 0; mt < 2; mt++) {
                int m = wm * 32 + mt * 16;
                const uint32_t* a0 = As + (m + g) * 36 + kk + t4;
                const uint32_t* a1 = As + (m + g + 8) * 36 + kk + t4;
                afr[mt][0] = a0[0]; afr[mt][1] = a1[0];
                afr[mt][2] = a0[4]; afr[mt][3] = a1[4];
            }
            #pragma unroll
            for (int nt = 0; nt < 4; nt++) {
                int n = wn * 32 + nt * 8 + g;
                bfr[nt][0] = Bs[(kk + t4) * 136 + n];
                bfr[nt][1] = Bs[(kk + t4 + 4) * 136 + n];
            }
            #pragma unroll
            for (int mt = 0; mt < 2; mt++)
                #pragma unroll
                for (int nt = 0; nt < 4; nt++)
                    mma_tf32(acc[mt][nt], afr[mt], bfr[nt]);
        }
        __syncthreads();
    }
    #pragma unroll
    for (int mt = 0; mt < 2; mt++) {
        int m = wm * 32 + mt * 16 + g;
        bool act0 = t < (lengths[m] - 1);
        bool act1 = t < (lengths[m + 8] - 1);
        float* o0 = out + ((size_t)m * TSTEP + t) * VOCAB;
        float* o1 = out + ((size_t)(m + 8) * TSTEP + t) * VOCAB;
        #pragma unroll
        for (int nt = 0; nt < 4; nt++) {
            int col = n0 + wn * 32 + nt * 8 + 2 * t4;
            if (col < VOCAB) {
                float b0 = bias[col];
                o0[col] = act0 ? (acc[mt][nt][0] + b0) : 0.f;
                o1[col] = act1 ? (acc[mt][nt][2] + b0) : 0.f;
            }
            if (col + 1 < VOCAB) {
                float b1 = bias[col + 1];
                o0[col + 1] = act0 ? (acc[mt][nt][1] + b1) : 0.f;
                o1[col + 1] = act1 ? (acc[mt][nt][3] + b1) : 0.f;
            }
        }
    }
}

extern "C" void kernel_launch(void* const* d_in, const int* in_sizes, int n_in,
                              void* d_out, int out_size) {
    const float* enc        = (const float*)d_in[0];
    const int*   captions   = (const int*)  d_in[1];
    const int*   lengths    = (const int*)  d_in[2];
    const float* emb        = (const float*)d_in[3];
    const float* enc_att_w  = (const float*)d_in[4];
    const float* enc_att_b  = (const float*)d_in[5];
    const float* dec_att_w  = (const float*)d_in[6];
    const float* dec_att_b  = (const float*)d_in[7];
    const float* full_att_w = (const float*)d_in[8];
    const float* full_att_b = (const float*)d_in[9];
    const float* w_ih       = (const float*)d_in[10];
    const float* b_ih       = (const float*)d_in[11];
    const float* w_hh       = (const float*)d_in[12];
    const float* b_hh       = (const float*)d_in[13];
    const float* init_h_w   = (const float*)d_in[14];
    const float* init_h_b   = (const float*)d_in[15];
    const float* init_c_w   = (const float*)d_in[16];
    const float* init_c_b   = (const float*)d_in[17];
    const float* f_beta_w   = (const float*)d_in[18];
    const float* f_beta_b   = (const float*)d_in[19];
    const float* fc_w       = (const float*)d_in[20];
    const float* fc_b       = (const float*)d_in[21];

    float* out       = (float*)d_out;
    float* out_alpha = out + (size_t)BATCH * TSTEP * VOCAB;

    mean_kernel<<<dim3(BATCH, ENCD / 256), 256>>>(enc);

    // h0 = mean @ init_h_w + b (K=2048 split 16), c0 likewise
    gemm64_tc<<<dim3(4, 16), 256>>>(XSEL_MEAN, ENCD, init_h_w, DECD, DECD,
                                    nullptr, 0, ENCD, nullptr, DECD, 128);
    finish64_kernel<<<BATCH, 512>>>(0, init_h_b, DECD, 16);
    gemm64_tc<<<dim3(4, 16), 256>>>(XSEL_MEAN, ENCD, init_c_w, DECD, DECD,
                                    nullptr, 0, ENCD, nullptr, DECD, 128);
    finish64_kernel<<<BATCH, 512>>>(1, init_c_b, DECD, 16);

    att1_tc<<<dim3((BATCH * PIX) / 128, ATTD / 128), 256>>>(enc, enc_att_w, enc_att_b);

    for (int t = 0; t < TSTEP; t++) {
        // fused [att2 | f_beta_pre] = h @ [dec_att_w | f_beta_w], N=2560, K=512 split 4
        gemm64_tc<<<dim3(20, 4), 256>>>(XSEL_H, DECD, dec_att_w, ATTD, ATTD,
                                        f_beta_w, ENCD, DECD, nullptr, 2560, 128);
        attn_scores_kernel<<<BATCH, 256>>>(dec_att_b, full_att_w, full_att_b,
                                           lengths, out_alpha, t, 4);
        ctx_gate_kernel<<<dim3(BATCH, 4), 256>>>(enc, f_beta_b, 4);
        build_x_kernel<<<BATCH, 256>>>(emb, captions, t);
        // gates = x @ [w_ih ; w_hh], N=2048, K=3072 split 8
        gemm64_tc<<<dim3(16, 8), 256>>>(XSEL_X, XDIM, w_ih, 2048, 2048,
                                        nullptr, 0, EMBD + ENCD, w_hh, 2048, 384);
        lstm_kernel<<<BATCH, 512>>>(b_ih, b_hh, lengths, t, 8);
        fc_tc<<<(VOCAB + 127) / 128, 256>>>(fc_w, fc_b, lengths, out, t);
    }
}

// round 4
// speedup vs baseline: 2.4759x; 1.5468x over previous
#include <cuda_runtime.h>
#include <cuda_fp16.h>
#include <cstdint>
#include <cstddef>

#define BATCH 64
#define PIX   196
#define ENCD  2048
#define ATTD  512
#define EMBD  512
#define DECD  512
#define VOCAB 20000
#define MAXLN 22
#define TSTEP 21
#define XDIM  3072
#define MROWS 1408   // 11*128, >= TSTEP*BATCH=1344

__device__ float g_att1[BATCH * PIX * ATTD];
__device__ __half2 g_ench[BATCH * PIX * (ENCD / 2)];
__device__ float g_mean[BATCH * ENCD];
__device__ float g_h[BATCH * DECD];
__device__ float g_c[BATCH * DECD];
__device__ float g_hall[MROWS * DECD];        // h_new per (t,b); rows >=1344 stay 0
__device__ float g_alpha[BATCH * PIX];
__device__ float g_x[BATCH * XDIM];
__device__ float g_part[16 * BATCH * 2560];

// ---------------------------------------------------------------------------
__device__ __forceinline__ uint32_t cvt_tf32(float f) {
    uint32_t u;
    asm("cvt.rna.tf32.f32 %0, %1;" : "=r"(u) : "f"(f));
    return u;
}
__device__ __forceinline__ void mma_tf32(float* d, const uint32_t* a, const uint32_t* b) {
    asm volatile(
        "mma.sync.aligned.m16n8k8.row.col.f32.tf32.tf32.f32 "
        "{%0,%1,%2,%3}, {%4,%5,%6,%7}, {%8,%9}, {%0,%1,%2,%3};\n"
        : "+f"(d[0]), "+f"(d[1]), "+f"(d[2]), "+f"(d[3])
        : "r"(a[0]), "r"(a[1]), "r"(a[2]), "r"(a[3]), "r"(b[0]), "r"(b[1]));
}
__device__ __forceinline__ void cp16(uint32_t dst, const void* src) {
    asm volatile("cp.async.cg.shared.global [%0], [%1], 16;\n" :: "r"(dst), "l"(src));
}
__device__ __forceinline__ void cp16z(uint32_t dst, const void* src, int srcbytes) {
    asm volatile("cp.async.cg.shared.global [%0], [%1], 16, %2;\n"
                 :: "r"(dst), "l"(src), "r"(srcbytes));
}
#define CP_COMMIT() asm volatile("cp.async.commit_group;\n")
#define CP_WAIT(n)  asm volatile("cp.async.wait_group %0;\n" :: "n"(n))

// ---------------------------------------------------------------------------
__global__ void mean_kernel(const float* __restrict__ enc) {
    int b = blockIdx.x;
    int e = blockIdx.y * 256 + threadIdx.x;
    const float* base = enc + (size_t)b * PIX * ENCD + e;
    float s = 0.f;
    #pragma unroll 4
    for (int p = 0; p < PIX; p++) s += base[(size_t)p * ENCD];
    g_mean[b * ENCD + e] = s * (1.0f / PIX);
}

__global__ void enc2h_kernel(const float* __restrict__ enc) {
    size_t i = (size_t)blockIdx.x * 256 + threadIdx.x;   // over float2 pairs
    const float2* src = (const float2*)enc;
    float2 v = src[i];
    g_ench[i] = __floats2half2_rn(v.x, v.y);
}

// ---------------------------------------------------------------------------
#define XSEL_H    0
#define XSEL_MEAN 1
#define XSEL_X    2

// M=64 tf32 GEMM, split-K, N-concat (Wa cols [0,na), Wb rest), K-concat
// (rows >= rows1 from W2k). Tile 64x128, 256 threads, cp.async 2-stage.
__global__ void gemm64_tc(int xsel, int ldx,
                          const float* __restrict__ Wa, int lda, int na,
                          const float* __restrict__ Wb, int ldb,
                          int rows1, const float* __restrict__ W2k,
                          int N, int KS)
{
    __shared__ float As[2][64 * 36];
    __shared__ float Bs[2][32 * 136];
    const float* X = (xsel == XSEL_H) ? g_h : (xsel == XSEL_MEAN) ? g_mean : g_x;
    int n0 = blockIdx.x * 128;
    int s  = blockIdx.y;
    int tid = threadIdx.x;
    int lane = tid & 31, warp = tid >> 5;
    int wm = warp >> 2, wn = warp & 3;
    int g = lane >> 2, t4 = lane & 3;

    const float* Wsel; int ld, coloff;
    if (n0 < na) { Wsel = Wa; ld = lda; coloff = n0; }
    else         { Wsel = Wb; ld = ldb; coloff = n0 - na; }

    float acc[2][4][4];
    #pragma unroll
    for (int i = 0; i < 2; i++)
        #pragma unroll
        for (int j = 0; j < 4; j++)
            #pragma unroll
            for (int q = 0; q < 4; q++) acc[i][j][q] = 0.f;

    int ar = tid >> 2, ak = (tid & 3) * 8;
    int bk = tid >> 3, bn = (tid & 7) * 16;
    uint32_t asb[2], bsb[2];
    #pragma unroll
    for (int u = 0; u < 2; u++) {
        asb[u] = (uint32_t)__cvta_generic_to_shared(&As[u][ar * 36 + ak]);
        bsb[u] = (uint32_t)__cvta_generic_to_shared(&Bs[u][bk * 136 + bn]);
    }
    int NC = KS / 32;

    auto issue = [&](int c, int buf) {
        int kbase = s * KS + c * 32;
        const float* xp = X + (size_t)ar * ldx + kbase + ak;
        cp16(asb[buf], xp);
        cp16(asb[buf] + 16, xp + 4);
        int kg = kbase + bk;
        const float* wrow = (kg < rows1)
            ? (Wsel + (size_t)kg * ld + coloff)
            : (W2k + (size_t)(kg - rows1) * ld + coloff);
        #pragma unroll
        for (int j = 0; j < 4; j++) cp16(bsb[buf] + j * 16, wrow + bn + j * 4);
        CP_COMMIT();
    };

    issue(0, 0);
    for (int c = 0; c < NC; c++) {
        int buf = c & 1;
        if (c + 1 < NC) { issue(c + 1, buf ^ 1); CP_WAIT(1); }
        else            { CP_WAIT(0); }
        __syncthreads();
        #pragma unroll
        for (int kk = 0; kk < 32; kk += 8) {
            uint32_t afr[2][4], bfr[4][2];
            #pragma unroll
            for (int mt = 0; mt < 2; mt++) {
                int m = wm * 32 + mt * 16;
                const float* a0 = &As[buf][(m + g) * 36 + kk + t4];
                const float* a1 = &As[buf][(m + g + 8) * 36 + kk + t4];
                afr[mt][0] = cvt_tf32(a0[0]); afr[mt][1] = cvt_tf32(a1[0]);
                afr[mt][2] = cvt_tf32(a0[4]); afr[mt][3] = cvt_tf32(a1[4]);
            }
            #pragma unroll
            for (int nt = 0; nt < 4; nt++) {
                int n = wn * 32 + nt * 8 + g;
                bfr[nt][0] = cvt_tf32(Bs[buf][(kk + t4) * 136 + n]);
                bfr[nt][1] = cvt_tf32(Bs[buf][(kk + t4 + 4) * 136 + n]);
            }
            #pragma unroll
            for (int mt = 0; mt < 2; mt++)
                #pragma unroll
                for (int nt = 0; nt < 4; nt++)
                    mma_tf32(acc[mt][nt], afr[mt], bfr[nt]);
        }
        __syncthreads();
    }
    #pragma unroll
    for (int mt = 0; mt < 2; mt++) {
        int row = wm * 32 + mt * 16 + g;
        #pragma unroll
        for (int nt = 0; nt < 4; nt++) {
            int col = n0 + wn * 32 + nt * 8 + 2 * t4;
            float* p0 = g_part + (size_t)(s * BATCH + row) * N + col;
            p0[0] = acc[mt][nt][0]; p0[1] = acc[mt][nt][1];
            float* p1 = p0 + (size_t)8 * N;
            p1[0] = acc[mt][nt][2]; p1[1] = acc[mt][nt][3];
        }
    }
}

__global__ void finish64_kernel(int dsel, const float* __restrict__ bias, int N, int nsplit) {
    float* dst = dsel ? g_c : g_h;
    int b = blockIdx.x;
    for (int n = threadIdx.x; n < N; n += blockDim.x) {
        float v = bias[n];
        for (int s = 0; s < nsplit; s++) v += g_part[(size_t)(s * BATCH + b) * N + n];
        dst[b * N + n] = v;
    }
}

// ---------------------------------------------------------------------------
// att1 (one-time): 12544x512 = enc(12544x2048) @ W(2048x512) + b, pipelined.
// ---------------------------------------------------------------------------
__global__ void att1_tc(const float* __restrict__ A, const float* __restrict__ W,
                        const float* __restrict__ bias) {
    __shared__ float As[2][128 * 36];
    __shared__ float Bs[2][32 * 136];
    int m0 = blockIdx.x * 128, n0 = blockIdx.y * 128;
    int tid = threadIdx.x;
    int lane = tid & 31, warp = tid >> 5;
    int wm = warp >> 2, wn = warp & 3;
    int g = lane >> 2, t4 = lane & 3;

    float acc[4][4][4];
    #pragma unroll
    for (int i = 0; i < 4; i++)
        #pragma unroll
        for (int j = 0; j < 4; j++)
            #pragma unroll
            for (int q = 0; q < 4; q++) acc[i][j][q] = 0.f;

    int ar = tid >> 1, ak = (tid & 1) * 16;
    int bk = tid >> 3, bn = (tid & 7) * 16;
    uint32_t asb[2], bsb[2];
    #pragma unroll
    for (int u = 0; u < 2; u++) {
        asb[u] = (uint32_t)__cvta_generic_to_shared(&As[u][ar * 36 + ak]);
        bsb[u] = (uint32_t)__cvta_generic_to_shared(&Bs[u][bk * 136 + bn]);
    }
    const int NC = ENCD / 32;

    auto issue = [&](int c, int buf) {
        int kbase = c * 32;
        const float* ap = A + (size_t)(m0 + ar) * ENCD + kbase + ak;
        #pragma unroll
        for (int j = 0; j < 4; j++) cp16(asb[buf] + j * 16, ap + j * 4);
        const float* wrow = W + (size_t)(kbase + bk) * ATTD + n0 + bn;
        #pragma unroll
        for (int j = 0; j < 4; j++) cp16(bsb[buf] + j * 16, wrow + j * 4);
        CP_COMMIT();
    };

    issue(0, 0);
    for (int c = 0; c < NC; c++) {
        int buf = c & 1;
        if (c + 1 < NC) { issue(c + 1, buf ^ 1); CP_WAIT(1); }
        else            { CP_WAIT(0); }
        __syncthreads();
        #pragma unroll
        for (int kk = 0; kk < 32; kk += 8) {
            uint32_t afr[4][4], bfr[4][2];
            #pragma unroll
            for (int mt = 0; mt < 4; mt++) {
                int m = wm * 64 + mt * 16;
                const float* a0 = &As[buf][(m + g) * 36 + kk + t4];
                const float* a1 = &As[buf][(m + g + 8) * 36 + kk + t4];
                afr[mt][0] = cvt_tf32(a0[0]); afr[mt][1] = cvt_tf32(a1[0]);
                afr[mt][2] = cvt_tf32(a0[4]); afr[mt][3] = cvt_tf32(a1[4]);
            }
            #pragma unroll
            for (int nt = 0; nt < 4; nt++) {
                int n = wn * 32 + nt * 8 + g;
                bfr[nt][0] = cvt_tf32(Bs[buf][(kk + t4) * 136 + n]);
                bfr[nt][1] = cvt_tf32(Bs[buf][(kk + t4 + 4) * 136 + n]);
            }
            #pragma unroll
            for (int mt = 0; mt < 4; mt++)
                #pragma unroll
                for (int nt = 0; nt < 4; nt++)
                    mma_tf32(acc[mt][nt], afr[mt], bfr[nt]);
        }
        __syncthreads();
    }
    #pragma unroll
    for (int mt = 0; mt < 4; mt++) {
        int row = m0 + wm * 64 + mt * 16 + g;
        #pragma unroll
        for (int nt = 0; nt < 4; nt++) {
            int col = n0 + wn * 32 + nt * 8 + 2 * t4;
            float b0 = bias[col], b1 = bias[col + 1];
            float* p0 = g_att1 + (size_t)row * ATTD + col;
            p0[0] = acc[mt][nt][0] + b0; p0[1] = acc[mt][nt][1] + b1;
            float* p1 = p0 + (size_t)8 * ATTD;
            p1[0] = acc[mt][nt][2] + b0; p1[1] = acc[mt][nt][3] + b1;
        }
    }
}

// ---------------------------------------------------------------------------
// scores + softmax (att2 = cols [0,512) of attW partials, stride 2560)
// ---------------------------------------------------------------------------
__global__ void attn_scores_kernel(const float* __restrict__ dec_att_b,
                                   const float* __restrict__ full_att_w,
                                   const float* __restrict__ full_att_b,
                                   const int* __restrict__ lengths,
                                   float* __restrict__ out_alpha, int t, int nsplit) {
    __shared__ float att2s[ATTD];
    __shared__ float fws[ATTD];
    __shared__ float sc[PIX];
    __shared__ float red[8];
    int b = blockIdx.x, tid = threadIdx.x;

    for (int a = tid; a < ATTD; a += 256) {
        float v = dec_att_b[a];
        for (int s = 0; s < nsplit; s++) v += g_part[(size_t)(s * BATCH + b) * 2560 + a];
        att2s[a] = v;
        fws[a] = full_att_w[a];
    }
    __syncthreads();

    int warp = tid >> 5, lane = tid & 31;
    for (int p = warp; p < PIX; p += 8) {
        const float* arow = g_att1 + ((size_t)(b * PIX + p)) * ATTD;
        float s = 0.f;
        for (int a = lane; a < ATTD; a += 32) {
            float v = arow[a] + att2s[a];
            s += fmaxf(v, 0.f) * fws[a];
        }
        #pragma unroll
        for (int o = 16; o; o >>= 1) s += __shfl_xor_sync(~0u, s, o);
        if (!lane) sc[p] = s + full_att_b[0];
    }
    __syncthreads();

    float v = (tid < PIX) ? sc[tid] : -1e30f;
    float m = v;
    #pragma unroll
    for (int o = 16; o; o >>= 1) m = fmaxf(m, __shfl_xor_sync(~0u, m, o));
    if (!lane) red[warp] = m;
    __syncthreads();
    if (tid == 0) {
        float mm = red[0];
        for (int i = 1; i < 8; i++) mm = fmaxf(mm, red[i]);
        red[0] = mm;
    }
    __syncthreads();
    float mx = red[0];
    float e = (tid < PIX) ? __expf(v - mx) : 0.f;
    float s2 = e;
    #pragma unroll
    for (int o = 16; o; o >>= 1) s2 += __shfl_xor_sync(~0u, s2, o);
    __syncthreads();
    if (!lane) red[warp] = s2;
    __syncthreads();
    if (tid == 0) {
        float ss = 0.f;
        for (int i = 0; i < 8; i++) ss += red[i];
        red[0] = ss;
    }
    __syncthreads();
    float inv = 1.f / red[0];
    if (tid < PIX) {
        float al = e * inv;
        g_alpha[b * PIX + tid] = al;
        bool active = t < (lengths[b] - 1);
        out_alpha[((size_t)b * TSTEP + t) * PIX + tid] = active ? al : 0.f;
    }
}

// ---------------------------------------------------------------------------
// context (fp16 enc) * gate -> x ctx slot. gate pre from partials cols [512,2560).
// grid(64,4), 256 thr; each thread 2 adjacent e via half2.
// ---------------------------------------------------------------------------
__global__ void ctx_gate_kernel(const float* __restrict__ f_beta_b, int nsplit) {
    __shared__ float als[PIX];
    int b = blockIdx.x, q = blockIdx.y, tid = threadIdx.x;
    if (tid < PIX) als[tid] = g_alpha[b * PIX + tid];
    __syncthreads();
    int e2 = q * 256 + tid;                     // half2 index in [0,1024)
    const __half2* base = g_ench + (size_t)b * PIX * (ENCD / 2) + e2;
    float c0 = 0.f, c1 = 0.f;
    #pragma unroll 4
    for (int p = 0; p < PIX; p++) {
        float2 v = __half22float2(base[(size_t)p * (ENCD / 2)]);
        c0 += als[p] * v.x;
        c1 += als[p] * v.y;
    }
    int e = e2 * 2;
    float gp0 = f_beta_b[e], gp1 = f_beta_b[e + 1];
    for (int s = 0; s < nsplit; s++) {
        const float* pp = g_part + (size_t)(s * BATCH + b) * 2560 + 512 + e;
        gp0 += pp[0]; gp1 += pp[1];
    }
    float ga0 = 1.f / (1.f + __expf(-gp0));
    float ga1 = 1.f / (1.f + __expf(-gp1));
    g_x[b * XDIM + EMBD + e]     = ga0 * c0;
    g_x[b * XDIM + EMBD + e + 1] = ga1 * c1;
}

// ---------------------------------------------------------------------------
// x init for t=0 (emb + h slots)
// ---------------------------------------------------------------------------
__global__ void init_x0_kernel(const float* __restrict__ emb,
                               const int* __restrict__ captions) {
    int b = blockIdx.x, d = threadIdx.x;
    int cap = captions[b * MAXLN];
    g_x[b * XDIM + d] = emb[(size_t)cap * EMBD + d];
    g_x[b * XDIM + EMBD + ENCD + d] = g_h[b * DECD + d];
}

// ---------------------------------------------------------------------------
// LSTM pointwise + store h_new to g_hall + prepare next step's x slots.
// ---------------------------------------------------------------------------
__global__ void lstm_kernel(const float* __restrict__ b_ih, const float* __restrict__ b_hh,
                            const int* __restrict__ lengths,
                            const float* __restrict__ emb, const int* __restrict__ captions,
                            int t, int nsplit) {
    int b = blockIdx.x, d = threadIdx.x;
    float g4[4];
    #pragma unroll
    for (int gi = 0; gi < 4; gi++) {
        int n = gi * 512 + d;
        float v = b_ih[n] + b_hh[n];
        for (int s = 0; s < nsplit; s++) v += g_part[(size_t)(s * BATCH + b) * 2048 + n];
        g4[gi] = v;
    }
    float ig = 1.f / (1.f + __expf(-g4[0]));
    float fg = 1.f / (1.f + __expf(-g4[1]));
    float gg = tanhf(g4[2]);
    float og = 1.f / (1.f + __expf(-g4[3]));
    float cold = g_c[b * DECD + d];
    float cn = fg * cold + ig * gg;
    float hn = og * tanhf(cn);
    g_hall[(size_t)(t * BATCH + b) * DECD + d] = hn;
    bool act = t < (lengths[b] - 1);
    float hold = g_h[b * DECD + d];
    float hcur = act ? hn : hold;
    if (act) {
        g_h[b * DECD + d] = hn;
        g_c[b * DECD + d] = cn;
    }
    if (t + 1 < TSTEP) {
        g_x[b * XDIM + EMBD + ENCD + d] = hcur;
        int cap = captions[b * MAXLN + t + 1];
        g_x[b * XDIM + d] = emb[(size_t)cap * EMBD + d];
    }
}

// ---------------------------------------------------------------------------
// Deferred fc: preds[(t,b)] = active ? hall @ fc_w + fc_b : 0.
// 128x128 tile, K=512, pipelined. grid(157, 11).
// ---------------------------------------------------------------------------
__global__ void fc_big(const float* __restrict__ W, const float* __restrict__ bias,
                       const int* __restrict__ lengths, float* __restrict__ out) {
    __shared__ float As[2][128 * 36];
    __shared__ float Bs[2][32 * 136];
    int n0 = blockIdx.x * 128, m0 = blockIdx.y * 128;
    int tid = threadIdx.x;
    int lane = tid & 31, warp = tid >> 5;
    int wm = warp >> 2, wn = warp & 3;
    int g = lane >> 2, t4 = lane & 3;
    bool full = (n0 + 128 <= VOCAB);

    float acc[4][4][4];
    #pragma unroll
    for (int i = 0; i < 4; i++)
        #pragma unroll
        for (int j = 0; j < 4; j++)
            #pragma unroll
            for (int q = 0; q < 4; q++) acc[i][j][q] = 0.f;

    int ar = tid >> 1, ak = (tid & 1) * 16;
    int bk = tid >> 3, bn = (tid & 7) * 16;
    uint32_t asb[2], bsb[2];
    #pragma unroll
    for (int u = 0; u < 2; u++) {
        asb[u] = (uint32_t)__cvta_generic_to_shared(&As[u][ar * 36 + ak]);
        bsb[u] = (uint32_t)__cvta_generic_to_shared(&Bs[u][bk * 136 + bn]);
    }
    const int NC = DECD / 32;

    auto issue = [&](int c, int buf) {
        int kbase = c * 32;
        const float* ap = g_hall + (size_t)(m0 + ar) * DECD + kbase + ak;
        #pragma unroll
        for (int j = 0; j < 4; j++) cp16(asb[buf] + j * 16, ap + j * 4);
        const float* wrow = W + (size_t)(kbase + bk) * VOCAB + n0 + bn;
        if (full) {
            #pragma unroll
            for (int j = 0; j < 4; j++) cp16(bsb[buf] + j * 16, wrow + j * 4);
        } else {
            #pragma unroll
            for (int j = 0; j < 4; j++) {
                int col = n0 + bn + j * 4;
                int vb = (VOCAB - col) * 4;
                vb = vb < 0 ? 0 : (vb > 16 ? 16 : vb);
                cp16z(bsb[buf] + j * 16, wrow + j * 4, vb);
            }
        }
        CP_COMMIT();
    };

    issue(0, 0);
    for (int c = 0; c < NC; c++) {
        int buf = c & 1;
        if (c + 1 < NC) { issue(c + 1, buf ^ 1); CP_WAIT(1); }
        else            { CP_WAIT(0); }
        __syncthreads();
        #pragma unroll
        for (int kk = 0; kk < 32; kk += 8) {
            uint32_t afr[4][4], bfr[4][2];
            #pragma unroll
            for (int mt = 0; mt < 4; mt++) {
                int m = wm * 64 + mt * 16;
                const float* a0 = &As[buf][(m + g) * 36 + kk + t4];
                const float* a1 = &As[buf][(m + g + 8) * 36 + kk + t4];
                afr[mt][0] = cvt_tf32(a0[0]); afr[mt][1] = cvt_tf32(a1[0]);
                afr[mt][2] = cvt_tf32(a0[4]); afr[mt][3] = cvt_tf32(a1[4]);
            }
            #pragma unroll
            for (int nt = 0; nt < 4; nt++) {
                int n = wn * 32 + nt * 8 + g;
                bfr[nt][0] = cvt_tf32(Bs[buf][(kk + t4) * 136 + n]);
                bfr[nt][1] = cvt_tf32(Bs[buf][(kk + t4 + 4) * 136 + n]);
            }
            #pragma unroll
            for (int mt = 0; mt < 4; mt++)
                #pragma unroll
                for (int nt = 0; nt < 4; nt++)
                    mma_tf32(acc[mt][nt], afr[mt], bfr[nt]);
        }
        __syncthreads();
    }
    #pragma unroll
    for (int mt = 0; mt < 4; mt++) {
        int row = m0 + wm * 64 + mt * 16 + g;
        #pragma unroll
        for (int rh = 0; rh < 2; rh++) {
            int r = row + rh * 8;
            if (r >= TSTEP * BATCH) continue;
            int tt = r / BATCH, bb = r % BATCH;
            bool act = tt < (lengths[bb] - 1);
            float* orow = out + ((size_t)bb * TSTEP + tt) * VOCAB;
            #pragma unroll
            for (int nt = 0; nt < 4; nt++) {
                int col = n0 + wn * 32 + nt * 8 + 2 * t4;
                if (col < VOCAB)
                    orow[col] = act ? (acc[mt][nt][rh * 2 + 0] + bias[col]) : 0.f;
                if (col + 1 < VOCAB)
                    orow[col + 1] = act ? (acc[mt][nt][rh * 2 + 1] + bias[col + 1]) : 0.f;
            }
        }
    }
}

// ---------------------------------------------------------------------------
extern "C" void kernel_launch(void* const* d_in, const int* in_sizes, int n_in,
                              void* d_out, int out_size) {
    const float* enc        = (const float*)d_in[0];
    const int*   captions   = (const int*)  d_in[1];
    const int*   lengths    = (const int*)  d_in[2];
    const float* emb        = (const float*)d_in[3];
    const float* enc_att_w  = (const float*)d_in[4];
    const float* enc_att_b  = (const float*)d_in[5];
    const float* dec_att_w  = (const float*)d_in[6];
    const float* dec_att_b  = (const float*)d_in[7];
    const float* full_att_w = (const float*)d_in[8];
    const float* full_att_b = (const float*)d_in[9];
    const float* w_ih       = (const float*)d_in[10];
    const float* b_ih       = (const float*)d_in[11];
    const float* w_hh       = (const float*)d_in[12];
    const float* b_hh       = (const float*)d_in[13];
    const float* init_h_w   = (const float*)d_in[14];
    const float* init_h_b   = (const float*)d_in[15];
    const float* init_c_w   = (const float*)d_in[16];
    const float* init_c_b   = (const float*)d_in[17];
    const float* f_beta_w   = (const float*)d_in[18];
    const float* f_beta_b   = (const float*)d_in[19];
    const float* fc_w       = (const float*)d_in[20];
    const float* fc_b       = (const float*)d_in[21];

    float* out       = (float*)d_out;
    float* out_alpha = out + (size_t)BATCH * TSTEP * VOCAB;

    // ---- setup ----
    enc2h_kernel<<<(BATCH * PIX * ENCD / 2) / 256, 256>>>(enc);
    mean_kernel<<<dim3(BATCH, ENCD / 256), 256>>>(enc);
    gemm64_tc<<<dim3(4, 16), 256>>>(XSEL_MEAN, ENCD, init_h_w, DECD, DECD,
                                    nullptr, 0, ENCD, nullptr, DECD, 128);
    finish64_kernel<<<BATCH, 512>>>(0, init_h_b, DECD, 16);
    gemm64_tc<<<dim3(4, 16), 256>>>(XSEL_MEAN, ENCD, init_c_w, DECD, DECD,
                                    nullptr, 0, ENCD, nullptr, DECD, 128);
    finish64_kernel<<<BATCH, 512>>>(1, init_c_b, DECD, 16);
    init_x0_kernel<<<BATCH, 512>>>(emb, captions);
    att1_tc<<<dim3((BATCH * PIX) / 128, ATTD / 128), 256>>>(enc, enc_att_w, enc_att_b);

    // ---- decode ----
    for (int t = 0; t < TSTEP; t++) {
        // [att2 | f_beta_pre] = h @ [dec_att_w | f_beta_w], N=2560, K=512 split 4
        gemm64_tc<<<dim3(20, 4), 256>>>(XSEL_H, DECD, dec_att_w, ATTD, ATTD,
                                        f_beta_w, ENCD, DECD, nullptr, 2560, 128);
        attn_scores_kernel<<<BATCH, 256>>>(dec_att_b, full_att_w, full_att_b,
                                           lengths, out_alpha, t, 4);
        ctx_gate_kernel<<<dim3(BATCH, 4), 256>>>(f_beta_b, 4);
        // gates = x @ [w_ih ; w_hh], N=2048, K=3072 split 8
        gemm64_tc<<<dim3(16, 8), 256>>>(XSEL_X, XDIM, w_ih, 2048, 2048,
                                        nullptr, 0, EMBD + ENCD, w_hh, 2048, 384);
        lstm_kernel<<<BATCH, 512>>>(b_ih, b_hh, lengths, emb, captions, t, 8);
    }

    // ---- deferred fc over all (t,b) ----
    fc_big<<<dim3((VOCAB + 127) / 128, MROWS / 128), 256>>>(fc_w, fc_b, lengths, out);
}